// round 6
// baseline (speedup 1.0000x reference)
#include <cuda_runtime.h>
#include <cuda_bf16.h>
#include <cstddef>

// ---------------- problem constants ----------------
#define CB   256      // batch (series)
#define CT   512      // train length
#define CW   465      // W = T - IN + 1
#define CWO  417      // Wo = T - OUT - IN + 1
#define CH   128      // hidden
#define CIN  48
#define COUT 48
#define CG   512      // 4*H
#define MTOT (CW*CB)  // 119040 time-batch rows
#define SLEN 560      // seasonality array length after extension

// output offsets (flattened tuple, return order, row-major)
#define OFF0 0                          // network_pred  (417,256,48)
#define OFF1 (CWO*CB*COUT)              // network_act   (417,256,48)
#define OFF2 (2*(CWO*CB*COUT))          // hold_out_pred (256,48)
#define OFF3 (OFF2 + CB*COUT)           // net_out_all   (465,256,48)
#define OFF4 (OFF3 + CW*CB*COUT)        // hold_out_act  (256,48)
#define OFF5 (OFF4 + CB*COUT)           // hold_out_act_norm (256,48)

// ---------------- device scratch ----------------
__device__ float g_levs [CB*CT];
__device__ float g_rlevs[CB*CT];
__device__ float g_seas [CB*SLEN];
__device__ float g_rseas[CB*SLEN];
__device__ float g_x0  [(size_t)MTOT*CIN];
__device__ float g_hA  [(size_t)MTOT*CH];
__device__ float g_hB  [(size_t)MTOT*CH];
__device__ float g_hC  [(size_t)MTOT*CH];
__device__ float g_hD  [(size_t)MTOT*CH];
__device__ float g_gates[(size_t)MTOT*CG];

__device__ __forceinline__ float fsig(float x) { return 1.f / (1.f + __expf(-x)); }

// ---------------- 1. exponential-smoothing scan ----------------
// one thread per series; sequential over T.
__global__ void scan_kernel(const float* __restrict__ train,
                            const float* __restrict__ ilev,
                            const float* __restrict__ iseas,
                            const float* __restrict__ iseason)
{
    int b = blockIdx.x * 32 + threadIdx.x;
    if (b >= CB) return;
    const float lev_sm  = 1.f / (1.f + expf(-ilev[0]));
    const float seas_sm = 1.f / (1.f + expf(-iseas[0]));
    float s0[24];
    #pragma unroll
    for (int j = 0; j < 24; j++) s0[j] = expf(iseason[j]);
    float sbuf[24];
    #pragma unroll
    for (int j = 0; j < 24; j++) sbuf[j] = s0[(j + 1) % 24];

    const float* tr = train + (size_t)b * CT;
    float* levs  = g_levs  + (size_t)b * CT;
    float* rlevs = g_rlevs + (size_t)b * CT;
    float* seas  = g_seas  + (size_t)b * SLEN;
    float* rseas = g_rseas + (size_t)b * SLEN;

    float lev = tr[0] / s0[0];
    levs[0] = lev; rlevs[0] = 1.f / lev;
    #pragma unroll
    for (int j = 0; j < 24; j++) { seas[j] = s0[j]; rseas[j] = 1.f / s0[j]; }
    seas[24] = s0[0]; rseas[24] = 1.f / s0[0];

    int head = 0;
    for (int t = 1; t < CT; t++) {
        float x  = tr[t];
        float st = sbuf[head];
        lev = lev_sm * (x / st) + (1.f - lev_sm) * lev;
        float sn = seas_sm * (x / lev) + (1.f - seas_sm) * st;
        sbuf[head] = sn;
        head = (head + 1 == 24) ? 0 : head + 1;
        levs[t] = lev; rlevs[t] = 1.f / lev;
        seas[t + 24] = sn; rseas[t + 24] = 1.f / sn;
    }
    // extension: seas[536+j] = seas[512+j]; ring buffer holds seas[512..535]
    #pragma unroll
    for (int j = 0; j < 24; j++) {
        float v = sbuf[(head + j) % 24];
        seas[536 + j] = v; rseas[536 + j] = 1.f / v;
    }
}

// ---------------- 2. window normalization ----------------
// builds win_in (g_x0, time-major rows) and writes network_act to d_out.
__global__ void windows_kernel(const float* __restrict__ train, float* __restrict__ out)
{
    const int total = CW * CB * CIN;
    for (int idx = blockIdx.x * blockDim.x + threadIdx.x; idx < total;
         idx += gridDim.x * blockDim.x) {
        int j = idx % CIN;
        int b = (idx / CIN) % CB;
        int w = idx / (CIN * CB);
        float rl = g_rlevs[b * CT + 47 + w];
        g_x0[((size_t)(w * CB + b)) * CIN + j] =
            train[b * CT + w + j] * g_rseas[b * SLEN + w + j] * rl;
        if (w < CWO) {
            out[OFF1 + ((size_t)(w * CB + b)) * COUT + j] =
                train[b * CT + w + 48 + j] * g_rseas[b * SLEN + w + 48 + j] * rl;
        }
    }
}

// ---------------- 3. tiled SGEMM: C[M,N] = A[M,K] @ Wt[N,K]^T + bias (+act) ----------------
// BM=128, BN=64, BK=16, 256 threads, 8x4 per thread.
// Optional dual-store: rows m < M2 also written to C2 (network_pred fusion).
__global__ __launch_bounds__(256) void sgemm_bias_act(
    const float* __restrict__ A, const float* __restrict__ Wt,
    const float* __restrict__ bias1, const float* __restrict__ bias2,
    float* __restrict__ C, int N, int K, int act,
    float* __restrict__ C2, int M2)
{
    __shared__ float As[16][128];
    __shared__ float Bs[16][68];

    const int tid = threadIdx.x;
    const int tx = tid & 15;          // n dir (x4)
    const int ty = tid >> 4;          // m dir (x8)
    const int m0 = blockIdx.y * 128;
    const int n0 = blockIdx.x * 64;

    const int ar = tid >> 2;          // 0..63
    const int ac = (tid & 3) * 4;     // 0,4,8,12

    float acc[8][4];
    #pragma unroll
    for (int i = 0; i < 8; i++)
        #pragma unroll
        for (int j = 0; j < 4; j++) acc[i][j] = 0.f;

    for (int kk = 0; kk < K; kk += 16) {
        float4 a0 = *(const float4*)&A[(size_t)(m0 + ar)      * K + kk + ac];
        float4 a1 = *(const float4*)&A[(size_t)(m0 + ar + 64) * K + kk + ac];
        float4 b0 = make_float4(0.f, 0.f, 0.f, 0.f);
        if (n0 + ar < N) b0 = *(const float4*)&Wt[(size_t)(n0 + ar) * K + kk + ac];

        __syncthreads();
        As[ac + 0][ar] = a0.x; As[ac + 1][ar] = a0.y;
        As[ac + 2][ar] = a0.z; As[ac + 3][ar] = a0.w;
        As[ac + 0][ar + 64] = a1.x; As[ac + 1][ar + 64] = a1.y;
        As[ac + 2][ar + 64] = a1.z; As[ac + 3][ar + 64] = a1.w;
        Bs[ac + 0][ar] = b0.x; Bs[ac + 1][ar] = b0.y;
        Bs[ac + 2][ar] = b0.z; Bs[ac + 3][ar] = b0.w;
        __syncthreads();

        #pragma unroll
        for (int k = 0; k < 16; k++) {
            float4 av0 = *(const float4*)&As[k][ty * 8];
            float4 av1 = *(const float4*)&As[k][ty * 8 + 4];
            float4 bv  = *(const float4*)&Bs[k][tx * 4];
            float av[8] = {av0.x, av0.y, av0.z, av0.w, av1.x, av1.y, av1.z, av1.w};
            float bb[4] = {bv.x, bv.y, bv.z, bv.w};
            #pragma unroll
            for (int i = 0; i < 8; i++)
                #pragma unroll
                for (int j = 0; j < 4; j++) acc[i][j] += av[i] * bb[j];
        }
    }

    #pragma unroll
    for (int j = 0; j < 4; j++) {
        int n = n0 + tx * 4 + j;
        if (n >= N) continue;
        float bb = bias1 ? bias1[n] : 0.f;
        if (bias2) bb += bias2[n];
        #pragma unroll
        for (int i = 0; i < 8; i++) {
            int m = m0 + ty * 8 + i;
            float v = acc[i][j] + bb;
            if (act) v = tanhf(v);
            C[(size_t)m * N + n] = v;
            if (C2 && m < M2) C2[(size_t)m * N + n] = v;
        }
    }
}

// ---------------- 4. dilated LSTM recurrence ----------------
// CTA: 512 threads, thread owns gate row n=tid; R chains (same phase p).
// W_hh row: k<64 in registers, k>=64 in smem [k][n].
// R=2 processes k in pairs so each h broadcast is one float4.
template <int R>
__global__ __launch_bounds__(512, 1) void rec_kernel(
    const float* __restrict__ gates, const float* __restrict__ whh,
    const float* __restrict__ resid, float* __restrict__ xout, int d)
{
    extern __shared__ float sm[];
    float* Wsm  = sm;                        // [64][512]
    float* actS = Wsm + 64 * 512;            // [512][R+1]
    float* hTs  = actS + 512 * (R + 1);      // [128][R]

    const int tid = threadIdx.x;
    const int cpp = 256 / R;                 // CTAs per phase
    const int p   = blockIdx.x / cpp;
    const int b0  = (blockIdx.x % cpp) * R;
    const int n   = tid;
    const bool isTanh = (n >= 256 && n < 384);

    float wreg[64];
    #pragma unroll
    for (int k = 0; k < 64; k++) wreg[k] = whh[n * 128 + k];
    for (int k = 0; k < 64; k++) Wsm[k * 512 + tid] = whh[n * 128 + 64 + k];

    for (int i = tid; i < 128 * R; i += 512) hTs[i] = 0.f;

    const int NP = (128 * R + 511) / 512;
    float creg[NP];
    #pragma unroll
    for (int it = 0; it < NP; it++) creg[it] = 0.f;

    __syncthreads();

    const int nq = (CW - p + d - 1) / d;
    for (int q = 0; q < nq; q++) {
        const int t = p + q * d;

        float gp[R];
        #pragma unroll
        for (int r = 0; r < R; r++)
            gp[r] = gates[((size_t)(t * CB + b0 + r)) * CG + n];

        float acc[R];
        #pragma unroll
        for (int r = 0; r < R; r++) acc[r] = 0.f;

        if (R == 2) {
            // register-weight half: k pairs, one float4 broadcast per pair
            #pragma unroll
            for (int k = 0; k < 64; k += 2) {
                float4 h4 = *(const float4*)(hTs + k * 2);
                acc[0] += wreg[k] * h4.x;     acc[1] += wreg[k] * h4.y;
                acc[0] += wreg[k + 1] * h4.z; acc[1] += wreg[k + 1] * h4.w;
            }
            // smem-weight half
            #pragma unroll
            for (int k = 0; k < 64; k += 2) {
                float4 h4 = *(const float4*)(hTs + (64 + k) * 2);
                float w0 = Wsm[k * 512 + tid];
                float w1 = Wsm[(k + 1) * 512 + tid];
                acc[0] += w0 * h4.x; acc[1] += w0 * h4.y;
                acc[0] += w1 * h4.z; acc[1] += w1 * h4.w;
            }
        } else {
            #pragma unroll
            for (int k = 0; k < 64; k++) {
                const float w = wreg[k];
                #pragma unroll
                for (int rr = 0; rr < R / 4; rr++) {
                    float4 h4 = *(const float4*)(hTs + k * R + rr * 4);
                    acc[rr*4+0] += w * h4.x; acc[rr*4+1] += w * h4.y;
                    acc[rr*4+2] += w * h4.z; acc[rr*4+3] += w * h4.w;
                }
            }
            #pragma unroll
            for (int k = 0; k < 64; k++) {
                const float w = Wsm[k * 512 + tid];
                #pragma unroll
                for (int rr = 0; rr < R / 4; rr++) {
                    float4 h4 = *(const float4*)(hTs + (64 + k) * R + rr * 4);
                    acc[rr*4+0] += w * h4.x; acc[rr*4+1] += w * h4.y;
                    acc[rr*4+2] += w * h4.z; acc[rr*4+3] += w * h4.w;
                }
            }
        }

        #pragma unroll
        for (int r = 0; r < R; r++) {
            float g = gp[r] + acc[r];
            float a = isTanh ? tanhf(g) : fsig(g);
            actS[n * (R + 1) + r] = a;
        }
        __syncthreads();

        // unit phase: cell/hidden updates
        #pragma unroll
        for (int it = 0; it < NP; it++) {
            int pi = tid + it * 512;
            if (128 * R >= 512 || pi < 128 * R) {
                int u = pi & 127, r = pi >> 7;
                float iv = actS[(u)       * (R + 1) + r];
                float fv = actS[(128 + u) * (R + 1) + r];
                float gv = actS[(256 + u) * (R + 1) + r];
                float ov = actS[(384 + u) * (R + 1) + r];
                float c  = fv * creg[it] + iv * gv;
                creg[it] = c;
                float h  = ov * tanhf(c);
                hTs[u * R + r] = h;
                size_t oi = ((size_t)(t * CB + b0 + r)) * CH + u;
                float o = h;
                if (resid) o += resid[oi];
                xout[oi] = o;
            }
        }
        __syncthreads();
    }
}

// ---------------- 5. epilogue: holdout outputs ----------------
__global__ void final_kernel(const float* __restrict__ val, float* __restrict__ out)
{
    int idx = blockIdx.x * blockDim.x + threadIdx.x;
    if (idx < CB * COUT) {
        int b = idx / COUT, j = idx % COUT;
        float last = out[OFF3 + ((size_t)((CW - 1) * CB + b)) * COUT + j];
        float hold = last * g_seas[b * SLEN + 512 + j] * g_levs[b * CT + 511];
        out[OFF2 + idx] = hold > 0.f ? hold : 0.f;
        float v = val[idx];
        out[OFF4 + idx] = v;
        out[OFF5 + idx] = v * g_rseas[b * SLEN + 512 + j] * g_rlevs[b * CT + 511];
    }
}

// ---------------- host ----------------
extern "C" void kernel_launch(void* const* d_in, const int* in_sizes, int n_in,
                              void* d_out, int out_size)
{
    const float* train = (const float*)d_in[0];
    const float* val   = (const float*)d_in[1];
    const float* ilev  = (const float*)d_in[3];
    const float* iseas = (const float*)d_in[4];
    const float* isea  = (const float*)d_in[5];
    const float* w_ih[4] = {(const float*)d_in[6],  (const float*)d_in[10],
                            (const float*)d_in[14], (const float*)d_in[18]};
    const float* w_hh[4] = {(const float*)d_in[7],  (const float*)d_in[11],
                            (const float*)d_in[15], (const float*)d_in[19]};
    const float* b_ih[4] = {(const float*)d_in[8],  (const float*)d_in[12],
                            (const float*)d_in[16], (const float*)d_in[20]};
    const float* b_hh[4] = {(const float*)d_in[9],  (const float*)d_in[13],
                            (const float*)d_in[17], (const float*)d_in[21]};
    const float* nl_w = (const float*)d_in[22];
    const float* nl_b = (const float*)d_in[23];
    const float* sc_w = (const float*)d_in[24];
    const float* sc_b = (const float*)d_in[25];
    float* out = (float*)d_out;

    void *px0, *phA, *phB, *phC, *phD, *pg;
    cudaGetSymbolAddress(&px0, g_x0);
    cudaGetSymbolAddress(&phA, g_hA);
    cudaGetSymbolAddress(&phB, g_hB);
    cudaGetSymbolAddress(&phC, g_hC);
    cudaGetSymbolAddress(&phD, g_hD);
    cudaGetSymbolAddress(&pg,  g_gates);
    float *x0 = (float*)px0, *hA = (float*)phA, *hB = (float*)phB,
          *hC = (float*)phC, *hD = (float*)phD, *gates = (float*)pg;

    const int smem2 = (64*512 + 512*3 + 128*2) * 4;   // 138240
    const int smem4 = (64*512 + 512*5 + 128*4) * 4;   // 143360
    cudaFuncSetAttribute(rec_kernel<2>, cudaFuncAttributeMaxDynamicSharedMemorySize, smem2);
    cudaFuncSetAttribute(rec_kernel<4>, cudaFuncAttributeMaxDynamicSharedMemorySize, smem4);

    // 1. ES scan
    scan_kernel<<<8, 32>>>(train, ilev, iseas, isea);
    // 2. windows (win_in + network_act)
    windows_kernel<<<4096, 256>>>(train, out);

    dim3 gGate(CG / 64, MTOT / 128);   // 8 x 930
    dim3 gNl(CH / 64, MTOT / 128);     // 2 x 930
    dim3 gSc(1, MTOT / 128);           // 48<64 -> 1 col-block with guards

    // cell 0 (d=1)
    sgemm_bias_act<<<gGate, 256>>>(x0, w_ih[0], b_ih[0], b_hh[0], gates, CG, CIN, 0, nullptr, 0);
    rec_kernel<2><<<128, 512, smem2>>>(gates, w_hh[0], nullptr, hA, 1);
    // cell 1 (d=2)
    sgemm_bias_act<<<gGate, 256>>>(hA, w_ih[1], b_ih[1], b_hh[1], gates, CG, CH, 0, nullptr, 0);
    rec_kernel<4><<<128, 512, smem4>>>(gates, w_hh[1], nullptr, hB, 2);
    // cell 2 (d=4)
    sgemm_bias_act<<<gGate, 256>>>(hB, w_ih[2], b_ih[2], b_hh[2], gates, CG, CH, 0, nullptr, 0);
    rec_kernel<4><<<256, 512, smem4>>>(gates, w_hh[2], nullptr, hC, 4);
    // cell 3 (d=8) + residual (x = h3 + h1_out = hB)
    sgemm_bias_act<<<gGate, 256>>>(hC, w_ih[3], b_ih[3], b_hh[3], gates, CG, CH, 0, nullptr, 0);
    rec_kernel<4><<<512, 512, smem4>>>(gates, w_hh[3], hB, hD, 8);
    // nonlinear layer: tanh(x @ nl_w^T + nl_b) -> reuse hC
    sgemm_bias_act<<<gNl, 256>>>(hD, nl_w, nl_b, nullptr, hC, CH, CH, 1, nullptr, 0);
    // scoring layer -> net_out_all region of d_out, dual-store first 417 windows
    // into network_pred (causality: network_pred == net_out_all[:417])
    sgemm_bias_act<<<gSc, 256>>>(hC, sc_w, sc_b, nullptr, out + OFF3, COUT, CH, 0,
                                 out + OFF0, CWO * CB);
    // epilogue (holdout rows only)
    final_kernel<<<64, 256>>>(val, out);
}

// round 7
// speedup vs baseline: 1.0657x; 1.0657x over previous
#include <cuda_runtime.h>
#include <cuda_bf16.h>
#include <cstddef>

// ---------------- problem constants ----------------
#define CB   256      // batch (series)
#define CT   512      // train length
#define CW   465      // W = T - IN + 1
#define CWO  417      // Wo = T - OUT - IN + 1
#define CH   128      // hidden
#define CIN  48
#define COUT 48
#define CG   512      // 4*H
#define MTOT (CW*CB)  // 119040 time-batch rows
#define SLEN 560      // seasonality array length after extension

// output offsets (flattened tuple, return order, row-major)
#define OFF0 0                          // network_pred  (417,256,48)
#define OFF1 (CWO*CB*COUT)              // network_act   (417,256,48)
#define OFF2 (2*(CWO*CB*COUT))          // hold_out_pred (256,48)
#define OFF3 (OFF2 + CB*COUT)           // net_out_all   (465,256,48)
#define OFF4 (OFF3 + CW*CB*COUT)        // hold_out_act  (256,48)
#define OFF5 (OFF4 + CB*COUT)           // hold_out_act_norm (256,48)

// ---------------- device scratch ----------------
__device__ float g_levs [CB*CT];
__device__ float g_rlevs[CB*CT];
__device__ float g_seas [CB*SLEN];
__device__ float g_rseas[CB*SLEN];
__device__ float g_x0  [(size_t)MTOT*CIN];
__device__ float g_hA  [(size_t)MTOT*CH];
__device__ float g_hB  [(size_t)MTOT*CH];
__device__ float g_hC  [(size_t)MTOT*CH];
__device__ float g_hD  [(size_t)MTOT*CH];
__device__ float g_gates[(size_t)MTOT*CG];

__device__ __forceinline__ float fsig(float x) { return 1.f / (1.f + __expf(-x)); }

// ---------------- packed f32x2 helpers (sm_103a FFMA2 via PTX) ----------------
typedef unsigned long long u64;

__device__ __forceinline__ u64 ffma2(u64 a, u64 b, u64 c) {
    u64 d;
    asm("fma.rn.f32x2 %0, %1, %2, %3;" : "=l"(d) : "l"(a), "l"(b), "l"(c));
    return d;
}
__device__ __forceinline__ u64 dup2(float x) {
    u64 r; asm("mov.b64 %0, {%1, %1};" : "=l"(r) : "f"(x)); return r;
}
__device__ __forceinline__ u64 pack2(float lo, float hi) {
    u64 r; asm("mov.b64 %0, {%1, %2};" : "=l"(r) : "f"(lo), "f"(hi)); return r;
}
__device__ __forceinline__ float2 unpack2(u64 v) {
    float2 f; asm("mov.b64 {%0, %1}, %2;" : "=f"(f.x), "=f"(f.y) : "l"(v)); return f;
}

// ---------------- 1. exponential-smoothing scan ----------------
__global__ void scan_kernel(const float* __restrict__ train,
                            const float* __restrict__ ilev,
                            const float* __restrict__ iseas,
                            const float* __restrict__ iseason)
{
    int b = blockIdx.x * 32 + threadIdx.x;
    if (b >= CB) return;
    const float lev_sm  = 1.f / (1.f + expf(-ilev[0]));
    const float seas_sm = 1.f / (1.f + expf(-iseas[0]));
    float s0[24];
    #pragma unroll
    for (int j = 0; j < 24; j++) s0[j] = expf(iseason[j]);
    float sbuf[24];
    #pragma unroll
    for (int j = 0; j < 24; j++) sbuf[j] = s0[(j + 1) % 24];

    const float* tr = train + (size_t)b * CT;
    float* levs  = g_levs  + (size_t)b * CT;
    float* rlevs = g_rlevs + (size_t)b * CT;
    float* seas  = g_seas  + (size_t)b * SLEN;
    float* rseas = g_rseas + (size_t)b * SLEN;

    float lev = tr[0] / s0[0];
    levs[0] = lev; rlevs[0] = 1.f / lev;
    #pragma unroll
    for (int j = 0; j < 24; j++) { seas[j] = s0[j]; rseas[j] = 1.f / s0[j]; }
    seas[24] = s0[0]; rseas[24] = 1.f / s0[0];

    int head = 0;
    for (int t = 1; t < CT; t++) {
        float x  = tr[t];
        float st = sbuf[head];
        lev = lev_sm * (x / st) + (1.f - lev_sm) * lev;
        float sn = seas_sm * (x / lev) + (1.f - seas_sm) * st;
        sbuf[head] = sn;
        head = (head + 1 == 24) ? 0 : head + 1;
        levs[t] = lev; rlevs[t] = 1.f / lev;
        seas[t + 24] = sn; rseas[t + 24] = 1.f / sn;
    }
    #pragma unroll
    for (int j = 0; j < 24; j++) {
        float v = sbuf[(head + j) % 24];
        seas[536 + j] = v; rseas[536 + j] = 1.f / v;
    }
}

// ---------------- 2. window normalization ----------------
__global__ void windows_kernel(const float* __restrict__ train, float* __restrict__ out)
{
    const int total = CW * CB * CIN;
    for (int idx = blockIdx.x * blockDim.x + threadIdx.x; idx < total;
         idx += gridDim.x * blockDim.x) {
        int j = idx % CIN;
        int b = (idx / CIN) % CB;
        int w = idx / (CIN * CB);
        float rl = g_rlevs[b * CT + 47 + w];
        g_x0[((size_t)(w * CB + b)) * CIN + j] =
            train[b * CT + w + j] * g_rseas[b * SLEN + w + j] * rl;
        if (w < CWO) {
            out[OFF1 + ((size_t)(w * CB + b)) * COUT + j] =
                train[b * CT + w + 48 + j] * g_rseas[b * SLEN + w + 48 + j] * rl;
        }
    }
}

// ---------------- 3. tiled SGEMM with FFMA2: C = A @ Wt^T + bias (+act) ----------------
// BM=128, BN=64, BK=16, 256 threads; acc packed over m-pairs (4x4 u64 = 8x4 f32).
__global__ __launch_bounds__(256) void sgemm_bias_act(
    const float* __restrict__ A, const float* __restrict__ Wt,
    const float* __restrict__ bias1, const float* __restrict__ bias2,
    float* __restrict__ C, int N, int K, int act,
    float* __restrict__ C2, int M2)
{
    __shared__ float As[16][128];
    __shared__ float Bs[16][68];

    const int tid = threadIdx.x;
    const int tx = tid & 15;          // n dir (x4)
    const int ty = tid >> 4;          // m dir (x8 = 4 pairs)
    const int m0 = blockIdx.y * 128;
    const int n0 = blockIdx.x * 64;

    const int ar = tid >> 2;          // 0..63
    const int ac = (tid & 3) * 4;     // 0,4,8,12

    u64 acc2[4][4];
    #pragma unroll
    for (int i = 0; i < 4; i++)
        #pragma unroll
        for (int j = 0; j < 4; j++) acc2[i][j] = 0ull;

    for (int kk = 0; kk < K; kk += 16) {
        float4 a0 = *(const float4*)&A[(size_t)(m0 + ar)      * K + kk + ac];
        float4 a1 = *(const float4*)&A[(size_t)(m0 + ar + 64) * K + kk + ac];
        float4 b0 = make_float4(0.f, 0.f, 0.f, 0.f);
        if (n0 + ar < N) b0 = *(const float4*)&Wt[(size_t)(n0 + ar) * K + kk + ac];

        __syncthreads();
        As[ac + 0][ar] = a0.x; As[ac + 1][ar] = a0.y;
        As[ac + 2][ar] = a0.z; As[ac + 3][ar] = a0.w;
        As[ac + 0][ar + 64] = a1.x; As[ac + 1][ar + 64] = a1.y;
        As[ac + 2][ar + 64] = a1.z; As[ac + 3][ar + 64] = a1.w;
        Bs[ac + 0][ar] = b0.x; Bs[ac + 1][ar] = b0.y;
        Bs[ac + 2][ar] = b0.z; Bs[ac + 3][ar] = b0.w;
        __syncthreads();

        #pragma unroll
        for (int k = 0; k < 16; k++) {
            ulonglong2 a01 = *(const ulonglong2*)&As[k][ty * 8];
            ulonglong2 a23 = *(const ulonglong2*)&As[k][ty * 8 + 4];
            float4 bv = *(const float4*)&Bs[k][tx * 4];
            u64 bb0 = dup2(bv.x), bb1 = dup2(bv.y), bb2 = dup2(bv.z), bb3 = dup2(bv.w);
            acc2[0][0] = ffma2(a01.x, bb0, acc2[0][0]);
            acc2[0][1] = ffma2(a01.x, bb1, acc2[0][1]);
            acc2[0][2] = ffma2(a01.x, bb2, acc2[0][2]);
            acc2[0][3] = ffma2(a01.x, bb3, acc2[0][3]);
            acc2[1][0] = ffma2(a01.y, bb0, acc2[1][0]);
            acc2[1][1] = ffma2(a01.y, bb1, acc2[1][1]);
            acc2[1][2] = ffma2(a01.y, bb2, acc2[1][2]);
            acc2[1][3] = ffma2(a01.y, bb3, acc2[1][3]);
            acc2[2][0] = ffma2(a23.x, bb0, acc2[2][0]);
            acc2[2][1] = ffma2(a23.x, bb1, acc2[2][1]);
            acc2[2][2] = ffma2(a23.x, bb2, acc2[2][2]);
            acc2[2][3] = ffma2(a23.x, bb3, acc2[2][3]);
            acc2[3][0] = ffma2(a23.y, bb0, acc2[3][0]);
            acc2[3][1] = ffma2(a23.y, bb1, acc2[3][1]);
            acc2[3][2] = ffma2(a23.y, bb2, acc2[3][2]);
            acc2[3][3] = ffma2(a23.y, bb3, acc2[3][3]);
        }
    }

    #pragma unroll
    for (int j = 0; j < 4; j++) {
        int n = n0 + tx * 4 + j;
        if (n >= N) continue;
        float bb = bias1 ? bias1[n] : 0.f;
        if (bias2) bb += bias2[n];
        #pragma unroll
        for (int i2 = 0; i2 < 4; i2++) {
            float2 v2 = unpack2(acc2[i2][j]);
            int m = m0 + ty * 8 + 2 * i2;
            float va = v2.x + bb;
            float vb = v2.y + bb;
            if (act) { va = tanhf(va); vb = tanhf(vb); }
            C[(size_t)m * N + n] = va;
            C[(size_t)(m + 1) * N + n] = vb;
            if (C2 && m < M2)     C2[(size_t)m * N + n] = va;
            if (C2 && m + 1 < M2) C2[(size_t)(m + 1) * N + n] = vb;
        }
    }
}

// ---------------- 4. dilated LSTM recurrence (FFMA2, k-pair packed) ----------------
// CTA: 512 threads, thread owns gate row n=tid; R chains (same phase p).
// h stored r-major: hTr[r][128] so (h[2j],h[2j+1]) is a contiguous u64.
// Weights: k<80 pre-packed pairs in regs (40 u64); k>=80 pre-packed pairs in smem.
#define WREG 80
#define WSM  (128 - WREG)   // 48 -> 24 u64 pairs

template <int R>
__global__ __launch_bounds__(512, 1) void rec_kernel(
    const float* __restrict__ gates, const float* __restrict__ whh,
    const float* __restrict__ resid, float* __restrict__ xout, int d)
{
    extern __shared__ float sm[];
    u64*   Wsm2 = (u64*)sm;                    // [WSM/2][512] pre-packed pairs
    float* actS = sm + WSM * 512;              // [512][R+1]
    float* hTr  = actS + 512 * (R + 1);        // [R][128]

    const int tid = threadIdx.x;
    const int cpp = 256 / R;                   // CTAs per phase
    const int p   = blockIdx.x / cpp;
    const int b0  = (blockIdx.x % cpp) * R;
    const int n   = tid;
    const bool isTanh = (n >= 256 && n < 384);

    // weights: 40 pre-packed pairs in registers (k = 0..79)
    u64 wreg2[WREG / 2];
    #pragma unroll
    for (int j = 0; j < WREG / 2; j++)
        wreg2[j] = pack2(whh[n * 128 + 2 * j], whh[n * 128 + 2 * j + 1]);
    // 24 pre-packed pairs in smem (k = 80..127), laid out [pair][n]
    for (int jj = 0; jj < WSM / 2; jj++)
        Wsm2[jj * 512 + tid] = pack2(whh[n * 128 + WREG + 2 * jj],
                                     whh[n * 128 + WREG + 2 * jj + 1]);

    for (int i = tid; i < 128 * R; i += 512) hTr[i] = 0.f;

    const int NP = (128 * R + 511) / 512;
    float creg[NP];
    #pragma unroll
    for (int it = 0; it < NP; it++) creg[it] = 0.f;

    __syncthreads();

    const int nq = (CW - p + d - 1) / d;
    for (int q = 0; q < nq; q++) {
        const int t = p + q * d;

        float gp[R];
        #pragma unroll
        for (int r = 0; r < R; r++)
            gp[r] = gates[((size_t)(t * CB + b0 + r)) * CG + n];

        u64 acc2[R];
        #pragma unroll
        for (int r = 0; r < R; r++) acc2[r] = 0ull;

        // register-weight half: k 0..79 as 20 quads (2 pairs per LDS.128)
        #pragma unroll
        for (int jj = 0; jj < WREG / 4; jj++) {
            #pragma unroll
            for (int r = 0; r < R; r++) {
                ulonglong2 hh = *(const ulonglong2*)&hTr[r * 128 + 4 * jj];
                acc2[r] = ffma2(wreg2[2 * jj],     hh.x, acc2[r]);
                acc2[r] = ffma2(wreg2[2 * jj + 1], hh.y, acc2[r]);
            }
        }
        // smem-weight half: k 80..127 as 12 quads
        #pragma unroll
        for (int jj = 0; jj < WSM / 2; jj += 2) {
            u64 w2a = Wsm2[jj * 512 + tid];
            u64 w2b = Wsm2[(jj + 1) * 512 + tid];
            #pragma unroll
            for (int r = 0; r < R; r++) {
                ulonglong2 hh = *(const ulonglong2*)&hTr[r * 128 + WREG + 2 * jj];
                acc2[r] = ffma2(w2a, hh.x, acc2[r]);
                acc2[r] = ffma2(w2b, hh.y, acc2[r]);
            }
        }

        #pragma unroll
        for (int r = 0; r < R; r++) {
            float2 s = unpack2(acc2[r]);
            float g = gp[r] + s.x + s.y;
            float a = isTanh ? tanhf(g) : fsig(g);
            actS[n * (R + 1) + r] = a;
        }
        __syncthreads();

        // unit phase: cell/hidden updates
        #pragma unroll
        for (int it = 0; it < NP; it++) {
            int pi = tid + it * 512;
            if (128 * R >= 512 || pi < 128 * R) {
                int u = pi & 127, r = pi >> 7;
                float iv = actS[(u)       * (R + 1) + r];
                float fv = actS[(128 + u) * (R + 1) + r];
                float gv = actS[(256 + u) * (R + 1) + r];
                float ov = actS[(384 + u) * (R + 1) + r];
                float c  = fv * creg[it] + iv * gv;
                creg[it] = c;
                float h  = ov * tanhf(c);
                hTr[r * 128 + u] = h;
                size_t oi = ((size_t)(t * CB + b0 + r)) * CH + u;
                float o = h;
                if (resid) o += resid[oi];
                xout[oi] = o;
            }
        }
        __syncthreads();
    }
}

// ---------------- 5. epilogue: holdout outputs ----------------
__global__ void final_kernel(const float* __restrict__ val, float* __restrict__ out)
{
    int idx = blockIdx.x * blockDim.x + threadIdx.x;
    if (idx < CB * COUT) {
        int b = idx / COUT, j = idx % COUT;
        float last = out[OFF3 + ((size_t)((CW - 1) * CB + b)) * COUT + j];
        float hold = last * g_seas[b * SLEN + 512 + j] * g_levs[b * CT + 511];
        out[OFF2 + idx] = hold > 0.f ? hold : 0.f;
        float v = val[idx];
        out[OFF4 + idx] = v;
        out[OFF5 + idx] = v * g_rseas[b * SLEN + 512 + j] * g_rlevs[b * CT + 511];
    }
}

// ---------------- host ----------------
extern "C" void kernel_launch(void* const* d_in, const int* in_sizes, int n_in,
                              void* d_out, int out_size)
{
    const float* train = (const float*)d_in[0];
    const float* val   = (const float*)d_in[1];
    const float* ilev  = (const float*)d_in[3];
    const float* iseas = (const float*)d_in[4];
    const float* isea  = (const float*)d_in[5];
    const float* w_ih[4] = {(const float*)d_in[6],  (const float*)d_in[10],
                            (const float*)d_in[14], (const float*)d_in[18]};
    const float* w_hh[4] = {(const float*)d_in[7],  (const float*)d_in[11],
                            (const float*)d_in[15], (const float*)d_in[19]};
    const float* b_ih[4] = {(const float*)d_in[8],  (const float*)d_in[12],
                            (const float*)d_in[16], (const float*)d_in[20]};
    const float* b_hh[4] = {(const float*)d_in[9],  (const float*)d_in[13],
                            (const float*)d_in[17], (const float*)d_in[21]};
    const float* nl_w = (const float*)d_in[22];
    const float* nl_b = (const float*)d_in[23];
    const float* sc_w = (const float*)d_in[24];
    const float* sc_b = (const float*)d_in[25];
    float* out = (float*)d_out;

    void *px0, *phA, *phB, *phC, *phD, *pg;
    cudaGetSymbolAddress(&px0, g_x0);
    cudaGetSymbolAddress(&phA, g_hA);
    cudaGetSymbolAddress(&phB, g_hB);
    cudaGetSymbolAddress(&phC, g_hC);
    cudaGetSymbolAddress(&phD, g_hD);
    cudaGetSymbolAddress(&pg,  g_gates);
    float *x0 = (float*)px0, *hA = (float*)phA, *hB = (float*)phB,
          *hC = (float*)phC, *hD = (float*)phD, *gates = (float*)pg;

    const int smem2 = (WSM*512 + 512*3 + 128*2) * 4;   // R=2
    const int smem4 = (WSM*512 + 512*5 + 128*4) * 4;   // R=4
    cudaFuncSetAttribute(rec_kernel<2>, cudaFuncAttributeMaxDynamicSharedMemorySize, smem2);
    cudaFuncSetAttribute(rec_kernel<4>, cudaFuncAttributeMaxDynamicSharedMemorySize, smem4);

    // 1. ES scan
    scan_kernel<<<8, 32>>>(train, ilev, iseas, isea);
    // 2. windows (win_in + network_act)
    windows_kernel<<<4096, 256>>>(train, out);

    dim3 gGate(CG / 64, MTOT / 128);   // 8 x 930
    dim3 gNl(CH / 64, MTOT / 128);     // 2 x 930
    dim3 gSc(1, MTOT / 128);           // 48<64 -> 1 col-block with guards

    // cell 0 (d=1)
    sgemm_bias_act<<<gGate, 256>>>(x0, w_ih[0], b_ih[0], b_hh[0], gates, CG, CIN, 0, nullptr, 0);
    rec_kernel<2><<<128, 512, smem2>>>(gates, w_hh[0], nullptr, hA, 1);
    // cell 1 (d=2)
    sgemm_bias_act<<<gGate, 256>>>(hA, w_ih[1], b_ih[1], b_hh[1], gates, CG, CH, 0, nullptr, 0);
    rec_kernel<4><<<128, 512, smem4>>>(gates, w_hh[1], nullptr, hB, 2);
    // cell 2 (d=4)
    sgemm_bias_act<<<gGate, 256>>>(hB, w_ih[2], b_ih[2], b_hh[2], gates, CG, CH, 0, nullptr, 0);
    rec_kernel<4><<<256, 512, smem4>>>(gates, w_hh[2], nullptr, hC, 4);
    // cell 3 (d=8) + residual (x = h3 + h1_out = hB)
    sgemm_bias_act<<<gGate, 256>>>(hC, w_ih[3], b_ih[3], b_hh[3], gates, CG, CH, 0, nullptr, 0);
    rec_kernel<4><<<512, 512, smem4>>>(gates, w_hh[3], hB, hD, 8);
    // nonlinear layer: tanh(x @ nl_w^T + nl_b) -> reuse hC
    sgemm_bias_act<<<gNl, 256>>>(hD, nl_w, nl_b, nullptr, hC, CH, CH, 1, nullptr, 0);
    // scoring layer -> net_out_all region, dual-store first 417 windows into
    // network_pred (causality: network_pred == net_out_all[:417])
    sgemm_bias_act<<<gSc, 256>>>(hC, sc_w, sc_b, nullptr, out + OFF3, COUT, CH, 0,
                                 out + OFF0, CWO * CB);
    // epilogue (holdout rows only)
    final_kernel<<<64, 256>>>(val, out);
}

// round 14
// speedup vs baseline: 1.0964x; 1.0288x over previous
#include <cuda_runtime.h>
#include <cuda_bf16.h>
#include <cstddef>

// ---------------- problem constants ----------------
#define CB   256      // batch (series)
#define CT   512      // train length
#define CW   465      // W = T - IN + 1
#define CWO  417      // Wo = T - OUT - IN + 1
#define CH   128      // hidden
#define CIN  48
#define COUT 48
#define CG   512      // 4*H
#define MTOT (CW*CB)  // 119040 time-batch rows
#define SLEN 560      // seasonality array length after extension

// output offsets (flattened tuple, return order, row-major)
#define OFF0 0                          // network_pred  (417,256,48)
#define OFF1 (CWO*CB*COUT)              // network_act   (417,256,48)
#define OFF2 (2*(CWO*CB*COUT))          // hold_out_pred (256,48)
#define OFF3 (OFF2 + CB*COUT)           // net_out_all   (465,256,48)
#define OFF4 (OFF3 + CW*CB*COUT)        // hold_out_act  (256,48)
#define OFF5 (OFF4 + CB*COUT)           // hold_out_act_norm (256,48)

// ---------------- device scratch ----------------
__device__ float g_levs [CB*CT];
__device__ float g_rlevs[CB*CT];
__device__ float g_seas [CB*SLEN];
__device__ float g_rseas[CB*SLEN];
__device__ float g_x0  [(size_t)MTOT*CIN];
__device__ float g_hA  [(size_t)MTOT*CH];
__device__ float g_hB  [(size_t)MTOT*CH];
__device__ float g_hC  [(size_t)MTOT*CH];
__device__ float g_hD  [(size_t)MTOT*CH];
__device__ float g_gates[(size_t)MTOT*CG];

__device__ __forceinline__ float fsig(float x)  { return 1.f / (1.f + __expf(-x)); }
// inf-safe fast tanh: e2x=inf -> 1-0=1; e2x=0 -> 1-2=-1
__device__ __forceinline__ float ftanh(float x) {
    float e = __expf(2.f * x);
    return 1.f - __fdividef(2.f, e + 1.f);
}

// ---------------- packed f32x2 helpers (sm_103a FFMA2 via PTX) ----------------
typedef unsigned long long u64;

__device__ __forceinline__ u64 ffma2(u64 a, u64 b, u64 c) {
    u64 d;
    asm("fma.rn.f32x2 %0, %1, %2, %3;" : "=l"(d) : "l"(a), "l"(b), "l"(c));
    return d;
}
__device__ __forceinline__ u64 dup2(float x) {
    u64 r; asm("mov.b64 %0, {%1, %1};" : "=l"(r) : "f"(x)); return r;
}
__device__ __forceinline__ u64 pack2(float lo, float hi) {
    u64 r; asm("mov.b64 %0, {%1, %2};" : "=l"(r) : "f"(lo), "f"(hi)); return r;
}
__device__ __forceinline__ float2 unpack2(u64 v) {
    float2 f; asm("mov.b64 {%0, %1}, %2;" : "=f"(f.x), "=f"(f.y) : "l"(v)); return f;
}

// ---------------- 1. exponential-smoothing scan ----------------
__global__ void scan_kernel(const float* __restrict__ train,
                            const float* __restrict__ ilev,
                            const float* __restrict__ iseas,
                            const float* __restrict__ iseason)
{
    int b = blockIdx.x * 32 + threadIdx.x;
    if (b >= CB) return;
    const float lev_sm  = 1.f / (1.f + expf(-ilev[0]));
    const float seas_sm = 1.f / (1.f + expf(-iseas[0]));
    float s0[24];
    #pragma unroll
    for (int j = 0; j < 24; j++) s0[j] = expf(iseason[j]);
    float sbuf[24];
    #pragma unroll
    for (int j = 0; j < 24; j++) sbuf[j] = s0[(j + 1) % 24];

    const float* tr = train + (size_t)b * CT;
    float* levs  = g_levs  + (size_t)b * CT;
    float* rlevs = g_rlevs + (size_t)b * CT;
    float* seas  = g_seas  + (size_t)b * SLEN;
    float* rseas = g_rseas + (size_t)b * SLEN;

    float lev = tr[0] / s0[0];
    levs[0] = lev; rlevs[0] = 1.f / lev;
    #pragma unroll
    for (int j = 0; j < 24; j++) { seas[j] = s0[j]; rseas[j] = 1.f / s0[j]; }
    seas[24] = s0[0]; rseas[24] = 1.f / s0[0];

    int head = 0;
    for (int t = 1; t < CT; t++) {
        float x  = tr[t];
        float st = sbuf[head];
        lev = lev_sm * (x / st) + (1.f - lev_sm) * lev;
        float sn = seas_sm * (x / lev) + (1.f - seas_sm) * st;
        sbuf[head] = sn;
        head = (head + 1 == 24) ? 0 : head + 1;
        levs[t] = lev; rlevs[t] = 1.f / lev;
        seas[t + 24] = sn; rseas[t + 24] = 1.f / sn;
    }
    #pragma unroll
    for (int j = 0; j < 24; j++) {
        float v = sbuf[(head + j) % 24];
        seas[536 + j] = v; rseas[536 + j] = 1.f / v;
    }
}

// ---------------- 2. window normalization ----------------
__global__ void windows_kernel(const float* __restrict__ train, float* __restrict__ out)
{
    const int total = CW * CB * CIN;
    for (int idx = blockIdx.x * blockDim.x + threadIdx.x; idx < total;
         idx += gridDim.x * blockDim.x) {
        int j = idx % CIN;
        int b = (idx / CIN) % CB;
        int w = idx / (CIN * CB);
        float rl = g_rlevs[b * CT + 47 + w];
        g_x0[((size_t)(w * CB + b)) * CIN + j] =
            train[b * CT + w + j] * g_rseas[b * SLEN + w + j] * rl;
        if (w < CWO) {
            out[OFF1 + ((size_t)(w * CB + b)) * COUT + j] =
                train[b * CT + w + 48 + j] * g_rseas[b * SLEN + w + 48 + j] * rl;
        }
    }
}

// ---------------- 3. pipelined SGEMM with FFMA2 ----------------
// BM=128, BN=64, BK=16, 256 threads; acc packed over m-pairs.
// Global loads for block kk+16 issued BEFORE compute on block kk (latency hidden).
__global__ __launch_bounds__(256) void sgemm_bias_act(
    const float* __restrict__ A, const float* __restrict__ Wt,
    const float* __restrict__ bias1, const float* __restrict__ bias2,
    float* __restrict__ C, int N, int K, int act,
    float* __restrict__ C2, int M2)
{
    __shared__ float As[16][128];
    __shared__ float Bs[16][68];

    const int tid = threadIdx.x;
    const int tx = tid & 15;          // n dir (x4)
    const int ty = tid >> 4;          // m dir (x8 = 4 pairs)
    const int m0 = blockIdx.y * 128;
    const int n0 = blockIdx.x * 64;

    const int ar = tid >> 2;          // 0..63
    const int ac = (tid & 3) * 4;     // 0,4,8,12

    u64 acc2[4][4];
    #pragma unroll
    for (int i = 0; i < 4; i++)
        #pragma unroll
        for (int j = 0; j < 4; j++) acc2[i][j] = 0ull;

    // preload block 0
    float4 a0 = *(const float4*)&A[(size_t)(m0 + ar)      * K + ac];
    float4 a1 = *(const float4*)&A[(size_t)(m0 + ar + 64) * K + ac];
    float4 b0 = make_float4(0.f, 0.f, 0.f, 0.f);
    if (n0 + ar < N) b0 = *(const float4*)&Wt[(size_t)(n0 + ar) * K + ac];

    for (int kk = 0; kk < K; kk += 16) {
        __syncthreads();
        As[ac + 0][ar] = a0.x; As[ac + 1][ar] = a0.y;
        As[ac + 2][ar] = a0.z; As[ac + 3][ar] = a0.w;
        As[ac + 0][ar + 64] = a1.x; As[ac + 1][ar + 64] = a1.y;
        As[ac + 2][ar + 64] = a1.z; As[ac + 3][ar + 64] = a1.w;
        Bs[ac + 0][ar] = b0.x; Bs[ac + 1][ar] = b0.y;
        Bs[ac + 2][ar] = b0.z; Bs[ac + 3][ar] = b0.w;
        __syncthreads();

        // prefetch next block (overlaps with compute below)
        if (kk + 16 < K) {
            a0 = *(const float4*)&A[(size_t)(m0 + ar)      * K + kk + 16 + ac];
            a1 = *(const float4*)&A[(size_t)(m0 + ar + 64) * K + kk + 16 + ac];
            b0 = make_float4(0.f, 0.f, 0.f, 0.f);
            if (n0 + ar < N) b0 = *(const float4*)&Wt[(size_t)(n0 + ar) * K + kk + 16 + ac];
        }

        #pragma unroll
        for (int k = 0; k < 16; k++) {
            ulonglong2 a01 = *(const ulonglong2*)&As[k][ty * 8];
            ulonglong2 a23 = *(const ulonglong2*)&As[k][ty * 8 + 4];
            float4 bv = *(const float4*)&Bs[k][tx * 4];
            u64 bb0 = dup2(bv.x), bb1 = dup2(bv.y), bb2 = dup2(bv.z), bb3 = dup2(bv.w);
            acc2[0][0] = ffma2(a01.x, bb0, acc2[0][0]);
            acc2[0][1] = ffma2(a01.x, bb1, acc2[0][1]);
            acc2[0][2] = ffma2(a01.x, bb2, acc2[0][2]);
            acc2[0][3] = ffma2(a01.x, bb3, acc2[0][3]);
            acc2[1][0] = ffma2(a01.y, bb0, acc2[1][0]);
            acc2[1][1] = ffma2(a01.y, bb1, acc2[1][1]);
            acc2[1][2] = ffma2(a01.y, bb2, acc2[1][2]);
            acc2[1][3] = ffma2(a01.y, bb3, acc2[1][3]);
            acc2[2][0] = ffma2(a23.x, bb0, acc2[2][0]);
            acc2[2][1] = ffma2(a23.x, bb1, acc2[2][1]);
            acc2[2][2] = ffma2(a23.x, bb2, acc2[2][2]);
            acc2[2][3] = ffma2(a23.x, bb3, acc2[2][3]);
            acc2[3][0] = ffma2(a23.y, bb0, acc2[3][0]);
            acc2[3][1] = ffma2(a23.y, bb1, acc2[3][1]);
            acc2[3][2] = ffma2(a23.y, bb2, acc2[3][2]);
            acc2[3][3] = ffma2(a23.y, bb3, acc2[3][3]);
        }
    }

    #pragma unroll
    for (int j = 0; j < 4; j++) {
        int n = n0 + tx * 4 + j;
        if (n >= N) continue;
        float bb = bias1 ? bias1[n] : 0.f;
        if (bias2) bb += bias2[n];
        #pragma unroll
        for (int i2 = 0; i2 < 4; i2++) {
            float2 v2 = unpack2(acc2[i2][j]);
            int m = m0 + ty * 8 + 2 * i2;
            float va = v2.x + bb;
            float vb = v2.y + bb;
            if (act) { va = ftanh(va); vb = ftanh(vb); }
            C[(size_t)m * N + n] = va;
            C[(size_t)(m + 1) * N + n] = vb;
            if (C2 && m < M2)     C2[(size_t)m * N + n] = va;
            if (C2 && m + 1 < M2) C2[(size_t)(m + 1) * N + n] = vb;
        }
    }
}

// ---------------- 4. dilated LSTM recurrence (FFMA2, gates prefetch) ----------------
#define WREG 72
#define WSM  (128 - WREG)   // 56 -> 28 u64 pairs

template <int R>
__global__ __launch_bounds__(512, 1) void rec_kernel(
    const float* __restrict__ gates, const float* __restrict__ whh,
    const float* __restrict__ resid, float* __restrict__ xout, int d)
{
    extern __shared__ float sm[];
    u64*   Wsm2 = (u64*)sm;                    // [WSM/2][512] pre-packed pairs
    float* actS = sm + WSM * 512;              // [512][R+1]
    float* hTr  = actS + 512 * (R + 1);        // [R][128]

    const int tid = threadIdx.x;
    const int cpp = 256 / R;                   // CTAs per phase
    const int p   = blockIdx.x / cpp;
    const int b0  = (blockIdx.x % cpp) * R;
    const int n   = tid;
    const bool isTanh = (n >= 256 && n < 384);

    // weights: 36 pre-packed pairs in registers (k = 0..71)
    u64 wreg2[WREG / 2];
    #pragma unroll
    for (int j = 0; j < WREG / 2; j++)
        wreg2[j] = pack2(whh[n * 128 + 2 * j], whh[n * 128 + 2 * j + 1]);
    // 28 pre-packed pairs in smem (k = 72..127), laid out [pair][n]
    for (int jj = 0; jj < WSM / 2; jj++)
        Wsm2[jj * 512 + tid] = pack2(whh[n * 128 + WREG + 2 * jj],
                                     whh[n * 128 + WREG + 2 * jj + 1]);

    for (int i = tid; i < 128 * R; i += 512) hTr[i] = 0.f;

    const int NP = (128 * R + 511) / 512;
    float creg[NP];
    #pragma unroll
    for (int it = 0; it < NP; it++) creg[it] = 0.f;

    __syncthreads();

    const int nq = (CW - p + d - 1) / d;

    // prefetch gates for q=0
    float gp[R];
    #pragma unroll
    for (int r = 0; r < R; r++)
        gp[r] = gates[((size_t)(p * CB + b0 + r)) * CG + n];

    for (int q = 0; q < nq; q++) {
        const int t = p + q * d;

        // prefetch gates for next step (lands under dot product + barriers)
        float gpn[R];
        {
            int qn = (q + 1 < nq) ? q + 1 : q;
            int tn = p + qn * d;
            #pragma unroll
            for (int r = 0; r < R; r++)
                gpn[r] = gates[((size_t)(tn * CB + b0 + r)) * CG + n];
        }

        u64 acc2[R];
        #pragma unroll
        for (int r = 0; r < R; r++) acc2[r] = 0ull;

        // register-weight half: k 0..71 as 18 quads
        #pragma unroll
        for (int jj = 0; jj < WREG / 4; jj++) {
            #pragma unroll
            for (int r = 0; r < R; r++) {
                ulonglong2 hh = *(const ulonglong2*)&hTr[r * 128 + 4 * jj];
                acc2[r] = ffma2(wreg2[2 * jj],     hh.x, acc2[r]);
                acc2[r] = ffma2(wreg2[2 * jj + 1], hh.y, acc2[r]);
            }
        }
        // smem-weight half: k 72..127 as 14 pair-pairs
        #pragma unroll
        for (int jj = 0; jj < WSM / 2; jj += 2) {
            u64 w2a = Wsm2[jj * 512 + tid];
            u64 w2b = Wsm2[(jj + 1) * 512 + tid];
            #pragma unroll
            for (int r = 0; r < R; r++) {
                ulonglong2 hh = *(const ulonglong2*)&hTr[r * 128 + WREG + 2 * jj];
                acc2[r] = ffma2(w2a, hh.x, acc2[r]);
                acc2[r] = ffma2(w2b, hh.y, acc2[r]);
            }
        }

        #pragma unroll
        for (int r = 0; r < R; r++) {
            float2 s = unpack2(acc2[r]);
            float g = gp[r] + s.x + s.y;
            float a = isTanh ? ftanh(g) : fsig(g);
            actS[n * (R + 1) + r] = a;
        }
        __syncthreads();

        // unit phase: cell/hidden updates
        #pragma unroll
        for (int it = 0; it < NP; it++) {
            int pi = tid + it * 512;
            if (128 * R >= 512 || pi < 128 * R) {
                int u = pi & 127, r = pi >> 7;
                float iv = actS[(u)       * (R + 1) + r];
                float fv = actS[(128 + u) * (R + 1) + r];
                float gv = actS[(256 + u) * (R + 1) + r];
                float ov = actS[(384 + u) * (R + 1) + r];
                float c  = fv * creg[it] + iv * gv;
                creg[it] = c;
                float h  = ov * ftanh(c);
                hTr[r * 128 + u] = h;
                size_t oi = ((size_t)(t * CB + b0 + r)) * CH + u;
                float o = h;
                if (resid) o += resid[oi];
                xout[oi] = o;
            }
        }
        __syncthreads();

        #pragma unroll
        for (int r = 0; r < R; r++) gp[r] = gpn[r];
    }
}

// ---------------- 5. epilogue: holdout outputs ----------------
__global__ void final_kernel(const float* __restrict__ val, float* __restrict__ out)
{
    int idx = blockIdx.x * blockDim.x + threadIdx.x;
    if (idx < CB * COUT) {
        int b = idx / COUT, j = idx % COUT;
        float last = out[OFF3 + ((size_t)((CW - 1) * CB + b)) * COUT + j];
        float hold = last * g_seas[b * SLEN + 512 + j] * g_levs[b * CT + 511];
        out[OFF2 + idx] = hold > 0.f ? hold : 0.f;
        float v = val[idx];
        out[OFF4 + idx] = v;
        out[OFF5 + idx] = v * g_rseas[b * SLEN + 512 + j] * g_rlevs[b * CT + 511];
    }
}

// ---------------- host ----------------
extern "C" void kernel_launch(void* const* d_in, const int* in_sizes, int n_in,
                              void* d_out, int out_size)
{
    const float* train = (const float*)d_in[0];
    const float* val   = (const float*)d_in[1];
    const float* ilev  = (const float*)d_in[3];
    const float* iseas = (const float*)d_in[4];
    const float* isea  = (const float*)d_in[5];
    const float* w_ih[4] = {(const float*)d_in[6],  (const float*)d_in[10],
                            (const float*)d_in[14], (const float*)d_in[18]};
    const float* w_hh[4] = {(const float*)d_in[7],  (const float*)d_in[11],
                            (const float*)d_in[15], (const float*)d_in[19]};
    const float* b_ih[4] = {(const float*)d_in[8],  (const float*)d_in[12],
                            (const float*)d_in[16], (const float*)d_in[20]};
    const float* b_hh[4] = {(const float*)d_in[9],  (const float*)d_in[13],
                            (const float*)d_in[17], (const float*)d_in[21]};
    const float* nl_w = (const float*)d_in[22];
    const float* nl_b = (const float*)d_in[23];
    const float* sc_w = (const float*)d_in[24];
    const float* sc_b = (const float*)d_in[25];
    float* out = (float*)d_out;

    void *px0, *phA, *phB, *phC, *phD, *pg;
    cudaGetSymbolAddress(&px0, g_x0);
    cudaGetSymbolAddress(&phA, g_hA);
    cudaGetSymbolAddress(&phB, g_hB);
    cudaGetSymbolAddress(&phC, g_hC);
    cudaGetSymbolAddress(&phD, g_hD);
    cudaGetSymbolAddress(&pg,  g_gates);
    float *x0 = (float*)px0, *hA = (float*)phA, *hB = (float*)phB,
          *hC = (float*)phC, *hD = (float*)phD, *gates = (float*)pg;

    const int smem2 = (WSM*512 + 512*3 + 128*2) * 4;   // R=2
    const int smem4 = (WSM*512 + 512*5 + 128*4) * 4;   // R=4
    cudaFuncSetAttribute(rec_kernel<2>, cudaFuncAttributeMaxDynamicSharedMemorySize, smem2);
    cudaFuncSetAttribute(rec_kernel<4>, cudaFuncAttributeMaxDynamicSharedMemorySize, smem4);

    // 1. ES scan
    scan_kernel<<<8, 32>>>(train, ilev, iseas, isea);
    // 2. windows (win_in + network_act)
    windows_kernel<<<4096, 256>>>(train, out);

    dim3 gGate(CG / 64, MTOT / 128);   // 8 x 930
    dim3 gNl(CH / 64, MTOT / 128);     // 2 x 930
    dim3 gSc(1, MTOT / 128);           // 48<64 -> 1 col-block with guards

    // cell 0 (d=1)
    sgemm_bias_act<<<gGate, 256>>>(x0, w_ih[0], b_ih[0], b_hh[0], gates, CG, CIN, 0, nullptr, 0);
    rec_kernel<2><<<128, 512, smem2>>>(gates, w_hh[0], nullptr, hA, 1);
    // cell 1 (d=2)
    sgemm_bias_act<<<gGate, 256>>>(hA, w_ih[1], b_ih[1], b_hh[1], gates, CG, CH, 0, nullptr, 0);
    rec_kernel<4><<<128, 512, smem4>>>(gates, w_hh[1], nullptr, hB, 2);
    // cell 2 (d=4)
    sgemm_bias_act<<<gGate, 256>>>(hB, w_ih[2], b_ih[2], b_hh[2], gates, CG, CH, 0, nullptr, 0);
    rec_kernel<4><<<256, 512, smem4>>>(gates, w_hh[2], nullptr, hC, 4);
    // cell 3 (d=8) + residual (x = h3 + h1_out = hB)
    sgemm_bias_act<<<gGate, 256>>>(hC, w_ih[3], b_ih[3], b_hh[3], gates, CG, CH, 0, nullptr, 0);
    rec_kernel<4><<<512, 512, smem4>>>(gates, w_hh[3], hB, hD, 8);
    // nonlinear layer: tanh(x @ nl_w^T + nl_b) -> reuse hC
    sgemm_bias_act<<<gNl, 256>>>(hD, nl_w, nl_b, nullptr, hC, CH, CH, 1, nullptr, 0);
    // scoring layer -> net_out_all region, dual-store first 417 windows into
    // network_pred (causality: network_pred == net_out_all[:417])
    sgemm_bias_act<<<gSc, 256>>>(hC, sc_w, sc_b, nullptr, out + OFF3, COUT, CH, 0,
                                 out + OFF0, CWO * CB);
    // epilogue (holdout rows only)
    final_kernel<<<64, 256>>>(val, out);
}